// round 10
// baseline (speedup 1.0000x reference)
#include <cuda_runtime.h>
#include <math.h>

#define Nn 50000
#define Ee 800000
#define Hh 96
#define DNn 128
#define DEe 64

typedef unsigned long long ULL;

// ---------------- device scratch ----------------
__device__ float d_h0[(size_t)Nn * Hh];
__device__ float d_xo0[(size_t)Nn * Hh];
__device__ float d_h1[(size_t)Nn * Hh];
__device__ float d_A[(size_t)Nn * Hh];
__device__ float d_B[(size_t)Nn * Hh];
__device__ float d_hs0[Nn], d_hd0[Nn], d_hs1[Nn], d_hd1[Nn], d_s0[Nn], d_s1[Nn];
__device__ int   d_cnt[Nn];
__device__ int   d_rowstart[Nn + 1];
__device__ int   d_cursor[Nn];
__device__ int   d_srcP[Ee];
__device__ float d_t0P[Ee], d_t1P[Ee];
__device__ float d_vae0[DEe], d_vae1[Hh], d_u[DEe], d_ws0[Hh], d_ws1[Hh], d_Cvec[Hh];
__device__ float d_M[DEe * Hh], d_WA0[Hh * Hh], d_WB0[Hh * Hh];
__device__ float d_c1s[1];

// ---------------- f32x2 + cp.async helpers ----------------
__device__ __forceinline__ ULL dup2(float v) {
    ULL r;
    asm("mov.b64 %0, {%1, %1};" : "=l"(r) : "f"(v));
    return r;
}
__device__ __forceinline__ ULL pack2(float x, float y) {
    ULL r;
    asm("mov.b64 %0, {%1, %2};" : "=l"(r) : "f"(x), "f"(y));
    return r;
}
__device__ __forceinline__ float2 unpack2(ULL v) {
    float2 f;
    asm("mov.b64 {%0, %1}, %2;" : "=f"(f.x), "=f"(f.y) : "l"(v));
    return f;
}
__device__ __forceinline__ void fma2(ULL& d, ULL a, ULL b) {
    asm("fma.rn.f32x2 %0, %1, %2, %0;" : "+l"(d) : "l"(a), "l"(b));
}
__device__ __forceinline__ void cp16(unsigned saddr, const void* gaddr) {
    asm volatile("cp.async.cg.shared.global [%0], [%1], 16;" :: "r"(saddr), "l"(gaddr));
}
#define CP_COMMIT asm volatile("cp.async.commit_group;" ::: "memory")
#define CP_WAIT0  asm volatile("cp.async.wait_group 0;" ::: "memory")

// ---------------- small prep kernels ----------------
__global__ void prep1_kernel(const float* __restrict__ we0, const float* __restrict__ ae0,
                             const float* __restrict__ we1, const float* __restrict__ ae1,
                             float* __restrict__ vae0, float* __restrict__ vae1) {
    int t = threadIdx.x;
    if (t < DEe) {
        float s = 0.f;
        const float* r = we0 + t * Hh;
        for (int j = 0; j < Hh; j++) s += r[j] * ae0[j];
        vae0[t] = s;
    }
    if (t < Hh) {
        float s = 0.f;
        const float* r = we1 + t * Hh;
        for (int j = 0; j < Hh; j++) s += r[j] * ae1[j];
        vae1[t] = s;
    }
}

__global__ void prep2_kernel(const float* __restrict__ ew0, const float* __restrict__ ew1,
                             const float* __restrict__ eb0, const float* __restrict__ eb1,
                             const float* __restrict__ vae1,
                             float* __restrict__ u, float* __restrict__ c1s,
                             float* __restrict__ ws0, float* __restrict__ ws1,
                             float* __restrict__ Cvec, float* __restrict__ M,
                             float* __restrict__ WA0, float* __restrict__ WB0) {
    int idx = blockIdx.x * blockDim.x + threadIdx.x;
    const float* ewb1 = ew1 + 192 * Hh;
    if (idx < 64) {
        float s = 0.f; const float* r = ew0 + (192 + idx) * Hh;
        for (int j = 0; j < Hh; j++) s += r[j] * vae1[j];
        u[idx] = s;
    } else if (idx == 64) {
        float s = 0.f;
        for (int j = 0; j < Hh; j++) s += eb0[j] * vae1[j];
        c1s[0] = s;
    } else if (idx < 161) {
        int k = idx - 65; float s = 0.f; const float* r = ew0 + k * Hh;
        for (int j = 0; j < Hh; j++) s += r[j] * vae1[j];
        ws0[k] = s;
    } else if (idx < 257) {
        int k = idx - 161; float s = 0.f; const float* r = ew0 + (96 + k) * Hh;
        for (int j = 0; j < Hh; j++) s += r[j] * vae1[j];
        ws1[k] = s;
    } else if (idx < 353) {
        int c = idx - 257; float s = eb1[c];
        for (int j = 0; j < Hh; j++) s += eb0[j] * ewb1[j * Hh + c];
        Cvec[c] = s;
    } else if (idx < 353 + 64 * 96) {
        int t = idx - 353; int k = t / 96, c = t % 96;
        float s = 0.f; const float* r = ew0 + (192 + k) * Hh;
        for (int j = 0; j < Hh; j++) s += r[j] * ewb1[j * Hh + c];
        M[t] = s;
    } else if (idx < 6497 + 96 * 96) {
        int t = idx - 6497; int k = t / 96, c = t % 96;
        float s = 0.f; const float* r = ew0 + k * Hh;
        for (int j = 0; j < Hh; j++) s += r[j] * ewb1[j * Hh + c];
        WA0[t] = s;
    } else if (idx < 15713 + 96 * 96) {
        int t = idx - 15713; int k = t / 96, c = t % 96;
        float s = 0.f; const float* r = ew0 + (96 + k) * Hh;
        for (int j = 0; j < Hh; j++) s += r[j] * ewb1[j * Hh + c];
        WB0[t] = s;
    }
}

// ---------------- CSR build ----------------
__global__ void zero_kernel(int* __restrict__ cnt, int* __restrict__ cursor) {
    int i = blockIdx.x * blockDim.x + threadIdx.x;
    if (i < Nn) { cnt[i] = 0; cursor[i] = 0; }
}

__global__ void hist_kernel(const int* __restrict__ dst, int* __restrict__ cnt) {
    int e = blockIdx.x * blockDim.x + threadIdx.x;
    if (e < Ee) atomicAdd(&cnt[dst[e]], 1);
}

__global__ void scan_kernel(const int* __restrict__ cnt, int* __restrict__ rowstart) {
    __shared__ int ssum[1024];
    const int T = 1024;
    const int CH = (Nn + T - 1) / T;
    int t = threadIdx.x;
    int base = t * CH;
    int s = 0;
    for (int i = 0; i < CH; i++) {
        int idx = base + i;
        if (idx < Nn) s += cnt[idx];
    }
    ssum[t] = s;
    __syncthreads();
    for (int off = 1; off < T; off <<= 1) {
        int v = 0;
        if (t >= off) v = ssum[t - off];
        __syncthreads();
        if (t >= off) ssum[t] += v;
        __syncthreads();
    }
    int run = (t == 0) ? 0 : ssum[t - 1];
    for (int i = 0; i < CH; i++) {
        int idx = base + i;
        if (idx < Nn) { rowstart[idx] = run; run += cnt[idx]; }
    }
    if (t == T - 1) rowstart[Nn] = ssum[T - 1];
}

// half-warp per edge
__global__ void scatter_kernel(const int* __restrict__ src, const int* __restrict__ dst,
                               const float* __restrict__ ea,
                               const int* __restrict__ rowstart, int* __restrict__ cursor,
                               int* __restrict__ srcP, float* __restrict__ t0P, float* __restrict__ t1P,
                               const float* __restrict__ vae0, const float* __restrict__ u) {
    int e = blockIdx.x * (blockDim.x >> 4) + (threadIdx.x >> 4);
    if (e >= Ee) return;
    int sl = threadIdx.x & 15;
    float4 v  = *(const float4*)(ea + (size_t)e * DEe + sl * 4);
    float4 w0 = *(const float4*)(vae0 + sl * 4);
    float4 w1 = *(const float4*)(u + sl * 4);
    float t0 = v.x * w0.x + v.y * w0.y + v.z * w0.z + v.w * w0.w;
    float t1 = v.x * w1.x + v.y * w1.y + v.z * w1.z + v.w * w1.w;
    for (int o = 8; o; o >>= 1) {
        t0 += __shfl_xor_sync(0xffffffffu, t0, o);
        t1 += __shfl_xor_sync(0xffffffffu, t1, o);
    }
    if (sl == 0) {
        int d = dst[e];
        int pos = rowstart[d] + atomicAdd(&cursor[d], 1);
        srcP[pos] = src[e];
        t0P[pos] = t0;
        t1P[pos] = t1;
    }
}

// ---------------- GEMM v7: cp.async double-buffered W, row-pair f32x2 accs ----------------
template<int K, int TWO>
__global__ void __launch_bounds__(192, 4) gemm64(const float* __restrict__ Xa, const float* __restrict__ Wa,
                                                 const float* __restrict__ Xb, const float* __restrict__ Wb,
                                                 float* __restrict__ C) {
    extern __shared__ float sm[];
    float* Xs = sm;                   // [K][64] k-major
    float* Ws = sm + 64 * K;          // [2][16][96]
    const int NC = K / 16;
    int tid = threadIdx.x;
    int cg = tid % 24, rg = tid / 24;
    int col = cg * 4, rbase = rg * 8;
    int r0 = blockIdx.x * 64;
    unsigned wsb = (unsigned)__cvta_generic_to_shared(Ws);

    ULL acc[4][4];
#pragma unroll
    for (int rp = 0; rp < 4; rp++)
#pragma unroll
        for (int c = 0; c < 4; c++) acc[rp][c] = 0ULL;

#pragma unroll
    for (int pass = 0; pass < TWO; pass++) {
        const float* X = pass ? Xb : Xa;
        const float* W = pass ? Wb : Wa;
        if (pass) __syncthreads();
        for (int idx = tid; idx < 64 * (K / 4); idx += 192) {
            int row = idx & 63;
            int kq = idx >> 6;
            float4 v = make_float4(0.f, 0.f, 0.f, 0.f);
            if (r0 + row < Nn) v = *(const float4*)(X + (size_t)(r0 + row) * K + kq * 4);
            Xs[(4 * kq + 0) * 64 + row] = v.x;
            Xs[(4 * kq + 1) * 64 + row] = v.y;
            Xs[(4 * kq + 2) * 64 + row] = v.z;
            Xs[(4 * kq + 3) * 64 + row] = v.w;
        }
        cp16(wsb + tid * 16, (const char*)W + tid * 16);
        cp16(wsb + (tid + 192) * 16, (const char*)W + (tid + 192) * 16);
        CP_COMMIT;
#pragma unroll
        for (int c = 0; c < NC; c++) {
            CP_WAIT0;
            __syncthreads();
            if (c + 1 < NC) {
                unsigned sb = wsb + ((c + 1) & 1) * 6144;
                const char* g = (const char*)(W + (c + 1) * 16 * 96);
                cp16(sb + tid * 16, g + tid * 16);
                cp16(sb + (tid + 192) * 16, g + (tid + 192) * 16);
                CP_COMMIT;
            }
            const float* xk = Xs + c * 16 * 64 + rbase;
            const float4* wrow = (const float4*)(Ws + (c & 1) * 1536) + cg;
#pragma unroll
            for (int k = 0; k < 16; k++) {
                float4 w4 = wrow[k * 24];
                ulonglong2 xa = *(const ulonglong2*)(xk + k * 64);
                ulonglong2 xb = *(const ulonglong2*)(xk + k * 64 + 4);
                ULL wd0 = dup2(w4.x), wd1 = dup2(w4.y), wd2 = dup2(w4.z), wd3 = dup2(w4.w);
                fma2(acc[0][0], xa.x, wd0); fma2(acc[0][1], xa.x, wd1); fma2(acc[0][2], xa.x, wd2); fma2(acc[0][3], xa.x, wd3);
                fma2(acc[1][0], xa.y, wd0); fma2(acc[1][1], xa.y, wd1); fma2(acc[1][2], xa.y, wd2); fma2(acc[1][3], xa.y, wd3);
                fma2(acc[2][0], xb.x, wd0); fma2(acc[2][1], xb.x, wd1); fma2(acc[2][2], xb.x, wd2); fma2(acc[2][3], xb.x, wd3);
                fma2(acc[3][0], xb.y, wd0); fma2(acc[3][1], xb.y, wd1); fma2(acc[3][2], xb.y, wd2); fma2(acc[3][3], xb.y, wd3);
            }
        }
    }

#pragma unroll
    for (int rp = 0; rp < 4; rp++) {
        float2 c0 = unpack2(acc[rp][0]);
        float2 c1 = unpack2(acc[rp][1]);
        float2 c2 = unpack2(acc[rp][2]);
        float2 c3 = unpack2(acc[rp][3]);
        int rowA = r0 + rbase + 2 * rp;
        if (rowA < Nn)
            *(float4*)(C + (size_t)rowA * 96 + col) = make_float4(c0.x, c1.x, c2.x, c3.x);
        if (rowA + 1 < Nn)
            *(float4*)(C + (size_t)(rowA + 1) * 96 + col) = make_float4(c0.y, c1.y, c2.y, c3.y);
    }
}

// ---------------- per-row dual/quad dots ----------------
__global__ void row_dots_kernel(const float* __restrict__ H,
                                const float* __restrict__ v1, const float* __restrict__ v2,
                                float* __restrict__ o1, float* __restrict__ o2) {
    int v = blockIdx.x * (blockDim.x >> 5) + (threadIdx.x >> 5);
    if (v >= Nn) return;
    int lane = threadIdx.x & 31;
    const float* hr = H + (size_t)v * Hh;
    float h0 = hr[lane], h1 = hr[lane + 32], h2 = hr[lane + 64];
    float d1 = h0 * v1[lane] + h1 * v1[lane + 32] + h2 * v1[lane + 64];
    float d2 = h0 * v2[lane] + h1 * v2[lane + 32] + h2 * v2[lane + 64];
    for (int o = 16; o; o >>= 1) {
        d1 += __shfl_xor_sync(0xffffffffu, d1, o);
        d2 += __shfl_xor_sync(0xffffffffu, d2, o);
    }
    if (lane == 0) { o1[v] = d1; o2[v] = d2; }
}

__global__ void row_dots4_kernel(const float* __restrict__ H1, const float* __restrict__ X0,
                                 const float* __restrict__ v1, const float* __restrict__ v2,
                                 const float* __restrict__ v3, const float* __restrict__ v4,
                                 float* __restrict__ o1, float* __restrict__ o2,
                                 float* __restrict__ o3, float* __restrict__ o4) {
    int v = blockIdx.x * (blockDim.x >> 5) + (threadIdx.x >> 5);
    if (v >= Nn) return;
    int lane = threadIdx.x & 31;
    const float* hr = H1 + (size_t)v * Hh;
    const float* xr = X0 + (size_t)v * Hh;
    float h0 = hr[lane], h1 = hr[lane + 32], h2 = hr[lane + 64];
    float x0 = xr[lane], x1 = xr[lane + 32], x2 = xr[lane + 64];
    float d1 = h0 * v1[lane] + h1 * v1[lane + 32] + h2 * v1[lane + 64];
    float d2 = h0 * v2[lane] + h1 * v2[lane + 32] + h2 * v2[lane + 64];
    float d3 = x0 * v3[lane] + x1 * v3[lane + 32] + x2 * v3[lane + 64];
    float d4 = x0 * v4[lane] + x1 * v4[lane + 32] + x2 * v4[lane + 64];
    for (int o = 16; o; o >>= 1) {
        d1 += __shfl_xor_sync(0xffffffffu, d1, o);
        d2 += __shfl_xor_sync(0xffffffffu, d2, o);
        d3 += __shfl_xor_sync(0xffffffffu, d3, o);
        d4 += __shfl_xor_sync(0xffffffffu, d4, o);
    }
    if (lane == 0) { o1[v] = d1; o2[v] = d2; o3[v] = d3; o4[v] = d4; }
}

// ---------------- GAT aggregation (warp per destination node) ----------------
__global__ void gat_aggregate_kernel(const int* __restrict__ rowstart, const int* __restrict__ srcP,
                                     float* __restrict__ tP, const float* __restrict__ h,
                                     const float* __restrict__ hs, const float* __restrict__ hd,
                                     const float* __restrict__ svec, const float* __restrict__ sself,
                                     const float* __restrict__ c1s,
                                     const float* __restrict__ bias, float* __restrict__ xout) {
    int v = blockIdx.x * (blockDim.x >> 5) + (threadIdx.x >> 5);
    if (v >= Nn) return;
    int lane = threadIdx.x & 31;
    int s = rowstart[v];
    int deg = rowstart[v + 1] - s;
    float hdv = hd[v];
    float nc = (c1s ? c1s[0] : 0.f) + (sself ? sself[v] : 0.f);
    const float* hv = h + (size_t)v * Hh;
    float den, a0, a1, a2;

    if (deg <= 32) {
        int u = 0;
        float ge = 0.f, l = -INFINITY;
        if (lane < deg) {
            u = srcP[s + lane];
            ge = tP[s + lane] + (svec ? svec[u] : 0.f) + nc;
            float ll = hs[u] + hdv + ge;
            l = ll > 0.f ? ll : 0.2f * ll;
        }
        float gs = (lane < deg) ? ge : 0.f;
        float mx = l;
        for (int o = 16; o; o >>= 1) {
            gs += __shfl_xor_sync(0xffffffffu, gs, o);
            mx = fmaxf(mx, __shfl_xor_sync(0xffffffffu, mx, o));
        }
        float lself = hs[v] + hdv + gs / (deg > 0 ? (float)deg : 1.f);
        lself = lself > 0.f ? lself : 0.2f * lself;
        float m = fmaxf(mx, lself);
        float p = __expf(l - m);
        float psum = p;
        for (int o = 16; o; o >>= 1) psum += __shfl_xor_sync(0xffffffffu, psum, o);
        float ps = __expf(lself - m);
        den = ps + psum;
        a0 = ps * hv[lane]; a1 = ps * hv[lane + 32]; a2 = ps * hv[lane + 64];
        for (int t0 = 0; t0 < deg; t0 += 8) {
            float pp[8]; int uu[8];
#pragma unroll
            for (int t = 0; t < 8; t++) {
                pp[t] = __shfl_sync(0xffffffffu, p, t0 + t);
                uu[t] = __shfl_sync(0xffffffffu, u, t0 + t);
            }
            int cnt8 = min(8, deg - t0);
#pragma unroll
            for (int t = 0; t < 8; t++) {
                if (t < cnt8) {
                    const float* hu = h + (size_t)uu[t] * Hh;
                    a0 = fmaf(pp[t], hu[lane], a0);
                    a1 = fmaf(pp[t], hu[lane + 32], a1);
                    a2 = fmaf(pp[t], hu[lane + 64], a2);
                }
            }
        }
    } else {
        float mx = -INFINITY, gs = 0.f;
        for (int i = lane; i < deg; i += 32) {
            int p_ = s + i;
            int uu = srcP[p_];
            float ge = tP[p_] + (svec ? svec[uu] : 0.f) + nc;
            float l = hs[uu] + hdv + ge;
            l = l > 0.f ? l : 0.2f * l;
            tP[p_] = l;
            gs += ge;
            mx = fmaxf(mx, l);
        }
        for (int o = 16; o; o >>= 1) {
            gs += __shfl_xor_sync(0xffffffffu, gs, o);
            mx = fmaxf(mx, __shfl_xor_sync(0xffffffffu, mx, o));
        }
        __syncwarp();
        float lself = hs[v] + hdv + gs / (float)deg;
        lself = lself > 0.f ? lself : 0.2f * lself;
        float m = fmaxf(mx, lself);
        den = __expf(lself - m);
        a0 = den * hv[lane]; a1 = den * hv[lane + 32]; a2 = den * hv[lane + 64];
        int i = 0;
        while (i < deg) {
            int cnt8 = min(8, deg - i);
            float lg[8]; int us[8];
#pragma unroll
            for (int t = 0; t < 8; t++)
                if (t < cnt8) { lg[t] = tP[s + i + t]; us[t] = srcP[s + i + t]; }
#pragma unroll
            for (int t = 0; t < 8; t++) {
                if (t < cnt8) {
                    float p_ = __expf(lg[t] - m);
                    den += p_;
                    const float* hu = h + (size_t)us[t] * Hh;
                    a0 = fmaf(p_, hu[lane], a0);
                    a1 = fmaf(p_, hu[lane + 32], a1);
                    a2 = fmaf(p_, hu[lane + 64], a2);
                }
            }
            i += cnt8;
        }
    }
    float inv = 1.f / den;
    float* xo = xout + (size_t)v * Hh;
    xo[lane]      = fmaf(a0, inv, bias[lane]);
    xo[lane + 32] = fmaf(a1, inv, bias[lane + 32]);
    xo[lane + 64] = fmaf(a2, inv, bias[lane + 64]);
}

// ---------------- final fused edge kernel v4: 64-edge tiles, 5 blocks/SM ----------------
// 192 threads = 24 col-groups(4 cols) x 8 edge-groups(8 edges). smem 41.5KB.
#define EF4_SMEM ((64 * 96 + 64 * 68) * 4 + 128 * 4)
__global__ void __launch_bounds__(192, 5) edge_final4(
    const float* __restrict__ ea, const int* __restrict__ src, const int* __restrict__ dst,
    const float* __restrict__ A, const float* __restrict__ Bm,
    const float* __restrict__ Mmat, const float* __restrict__ Cvec,
    float* __restrict__ out) {
    extern __shared__ float sm[];
    float* Ms = sm;                       // [64][96]
    float* east = sm + 64 * 96;           // [64][68] transposed ea tile
    int* ss = (int*)(east + 64 * 68);     // [64]
    int* dd = ss + 64;
    int tid = threadIdx.x;
    int cg = tid % 24, eg = tid / 24;
    int col = 4 * cg;
    int ebase = eg * 8;

    for (int idx = tid; idx < 64 * 96; idx += 192) Ms[idx] = Mmat[idx];
    size_t e0 = (size_t)blockIdx.x * 64;
    for (int idx = tid; idx < 2048; idx += 192) {
        int e = idx >> 5;
        int k = (idx & 31) << 1;
        float2 vv = *(const float2*)(ea + (e0 + e) * 64 + k);
        east[k * 68 + e] = vv.x;
        east[(k + 1) * 68 + e] = vv.y;
    }
    if (tid < 64) { ss[tid] = src[e0 + tid]; dd[tid] = dst[e0 + tid]; }
    __syncthreads();

    float4 cv = *(const float4*)(Cvec + col);
    ULL acc[4][4];
#pragma unroll
    for (int p = 0; p < 4; p++) {
        int ei = ebase + 2 * p;
        float4 aL = *(const float4*)(A + (size_t)ss[ei] * 96 + col);
        float4 aR = *(const float4*)(A + (size_t)ss[ei + 1] * 96 + col);
        float4 bL = *(const float4*)(Bm + (size_t)dd[ei] * 96 + col);
        float4 bR = *(const float4*)(Bm + (size_t)dd[ei + 1] * 96 + col);
        acc[p][0] = pack2(cv.x + aL.x + bL.x, cv.x + aR.x + bR.x);
        acc[p][1] = pack2(cv.y + aL.y + bL.y, cv.y + aR.y + bR.y);
        acc[p][2] = pack2(cv.z + aL.z + bL.z, cv.z + aR.z + bR.z);
        acc[p][3] = pack2(cv.w + aL.w + bL.w, cv.w + aR.w + bR.w);
    }

    const float* mrow = Ms + col;
    const float* erow = east + ebase;
#pragma unroll 2
    for (int k = 0; k < 64; k++) {
        float4 m4 = *(const float4*)(mrow + k * 96);
        ULL M0 = dup2(m4.x), M1 = dup2(m4.y), M2 = dup2(m4.z), M3 = dup2(m4.w);
        const float* er = erow + k * 68;
        ulonglong2 q0 = *(const ulonglong2*)(er);       // edge pairs 0,1
        ulonglong2 q1 = *(const ulonglong2*)(er + 4);   // edge pairs 2,3
        fma2(acc[0][0], q0.x, M0); fma2(acc[0][1], q0.x, M1); fma2(acc[0][2], q0.x, M2); fma2(acc[0][3], q0.x, M3);
        fma2(acc[1][0], q0.y, M0); fma2(acc[1][1], q0.y, M1); fma2(acc[1][2], q0.y, M2); fma2(acc[1][3], q0.y, M3);
        fma2(acc[2][0], q1.x, M0); fma2(acc[2][1], q1.x, M1); fma2(acc[2][2], q1.x, M2); fma2(acc[2][3], q1.x, M3);
        fma2(acc[3][0], q1.y, M0); fma2(acc[3][1], q1.y, M1); fma2(acc[3][2], q1.y, M2); fma2(acc[3][3], q1.y, M3);
    }

#pragma unroll
    for (int p = 0; p < 4; p++) {
        float2 f0 = unpack2(acc[p][0]);
        float2 f1 = unpack2(acc[p][1]);
        float2 f2 = unpack2(acc[p][2]);
        float2 f3 = unpack2(acc[p][3]);
        size_t eA = e0 + ebase + 2 * p;
        *(float4*)(out + eA * 96 + col)       = make_float4(f0.x, f1.x, f2.x, f3.x);
        *(float4*)(out + (eA + 1) * 96 + col) = make_float4(f0.y, f1.y, f2.y, f3.y);
    }
}

// ---------------- host ----------------
static void* sym(const void* s) {
    void* p = nullptr;
    cudaGetSymbolAddress(&p, (const void*)s);
    return p;
}

extern "C" void kernel_launch(void* const* d_in, const int* in_sizes, int n_in,
                              void* d_out, int out_size) {
    const float* x    = (const float*)d_in[0];
    const int*   ei   = (const int*)d_in[1];
    const float* ea   = (const float*)d_in[2];
    const float* w0   = (const float*)d_in[3];
    const float* we0  = (const float*)d_in[4];
    const float* as0  = (const float*)d_in[5];
    const float* ad0  = (const float*)d_in[6];
    const float* ae0  = (const float*)d_in[7];
    const float* b0   = (const float*)d_in[8];
    const float* ew0  = (const float*)d_in[9];
    const float* eb0  = (const float*)d_in[10];
    const float* w1   = (const float*)d_in[11];
    const float* we1  = (const float*)d_in[12];
    const float* as1  = (const float*)d_in[13];
    const float* ad1  = (const float*)d_in[14];
    const float* ae1  = (const float*)d_in[15];
    const float* b1   = (const float*)d_in[16];
    const float* ew1  = (const float*)d_in[17];
    const float* eb1  = (const float*)d_in[18];

    const int* src = ei;
    const int* dst = ei + Ee;

    float* h0   = (float*)sym(d_h0);
    float* xo0  = (float*)sym(d_xo0);
    float* h1   = (float*)sym(d_h1);
    float* A    = (float*)sym(d_A);
    float* B    = (float*)sym(d_B);
    float* hs0  = (float*)sym(d_hs0);
    float* hd0  = (float*)sym(d_hd0);
    float* hs1  = (float*)sym(d_hs1);
    float* hd1  = (float*)sym(d_hd1);
    float* s0   = (float*)sym(d_s0);
    float* s1   = (float*)sym(d_s1);
    int*   cnt  = (int*)sym(d_cnt);
    int*   rowstart = (int*)sym(d_rowstart);
    int*   cursor   = (int*)sym(d_cursor);
    int*   srcP = (int*)sym(d_srcP);
    float* t0P  = (float*)sym(d_t0P);
    float* t1P  = (float*)sym(d_t1P);
    float* vae0 = (float*)sym(d_vae0);
    float* vae1 = (float*)sym(d_vae1);
    float* u    = (float*)sym(d_u);
    float* ws0  = (float*)sym(d_ws0);
    float* ws1  = (float*)sym(d_ws1);
    float* Cvec = (float*)sym(d_Cvec);
    float* M    = (float*)sym(d_M);
    float* WA0  = (float*)sym(d_WA0);
    float* WB0  = (float*)sym(d_WB0);
    float* c1s  = (float*)sym(d_c1s);

    float* x1_out = (float*)d_out;                       // [Nn,96]
    float* ea_out = (float*)d_out + (size_t)Nn * Hh;     // [Ee,96]

    const int SM128 = (64 * 128 + 2 * 16 * 96) * 4;   // 44KB
    const int SM96  = (64 * 96 + 2 * 16 * 96) * 4;    // 36KB

    const int GB = (Nn + 63) / 64;

    // prep + CSR
    zero_kernel<<<(Nn + 255) / 256, 256>>>(cnt, cursor);
    prep1_kernel<<<1, 96>>>(we0, ae0, we1, ae1, vae0, vae1);
    prep2_kernel<<<(24929 + 127) / 128, 128>>>(ew0, ew1, eb0, eb1, vae1,
                                               u, c1s, ws0, ws1, Cvec, M, WA0, WB0);
    gemm64<128, 1><<<GB, 192, SM128>>>(x, w0, nullptr, nullptr, h0);          // h0 = x@w0 (profiled)
    hist_kernel<<<Ee / 256, 256>>>(dst, cnt);
    scan_kernel<<<1, 1024>>>(cnt, rowstart);
    scatter_kernel<<<Ee / 16, 256>>>(src, dst, ea, rowstart, cursor, srcP, t0P, t1P, vae0, u);

    // layer 0
    row_dots_kernel<<<Nn / 8, 256>>>(h0, as0, ad0, hs0, hd0);
    gat_aggregate_kernel<<<Nn / 8, 256>>>(rowstart, srcP, t0P, h0, hs0, hd0,
                                          nullptr, nullptr, nullptr, b0, xo0);

    // layer 1 node path
    gemm64<96, 1><<<GB, 192, SM96>>>(xo0, w1, nullptr, nullptr, h1);          // h1 = xo0@w1
    row_dots4_kernel<<<Nn / 8, 256>>>(h1, xo0, as1, ad1, ws0, ws1, hs1, hd1, s0, s1);
    gat_aggregate_kernel<<<Nn / 8, 256>>>(rowstart, srcP, t1P, h1, hs1, hd1,
                                          s0, s1, c1s, b1, x1_out);

    // A = x1@ew1_top + xo0@WA0 ; B = x1@ew1_mid + xo0@WB0
    gemm64<96, 2><<<GB, 192, SM96>>>(x1_out, ew1, xo0, WA0, A);
    gemm64<96, 2><<<GB, 192, SM96>>>(x1_out, ew1 + 96 * 96, xo0, WB0, B);

    // fused final edge output (64-edge tiles)
    edge_final4<<<Ee / 64, 192, EF4_SMEM>>>(ea, src, dst, A, B, M, Cvec, ea_out);
}

// round 11
// speedup vs baseline: 1.0565x; 1.0565x over previous
#include <cuda_runtime.h>
#include <math.h>

#define Nn 50000
#define Ee 800000
#define Hh 96
#define DNn 128
#define DEe 64

typedef unsigned long long ULL;

// ---------------- device scratch ----------------
__device__ float d_h0[(size_t)Nn * Hh];
__device__ float d_xo0[(size_t)Nn * Hh];
__device__ float d_h1[(size_t)Nn * Hh];
__device__ float d_A[(size_t)Nn * Hh];
__device__ float d_B[(size_t)Nn * Hh];
__device__ float d_hs0[Nn], d_hd0[Nn], d_hs1[Nn], d_hd1[Nn], d_s0[Nn], d_s1[Nn];
__device__ int   d_cnt[Nn];
__device__ int   d_rowstart[Nn + 1];
__device__ int   d_cursor[Nn];
__device__ int   d_srcP[Ee];
__device__ float d_t0P[Ee], d_t1P[Ee];
__device__ float d_vae0[DEe], d_vae1[Hh], d_u[DEe], d_ws0[Hh], d_ws1[Hh], d_Cvec[Hh];
__device__ float d_M[DEe * Hh], d_WA0[Hh * Hh], d_WB0[Hh * Hh];
__device__ float d_c1s[1];

// ---------------- f32x2 + cp.async helpers ----------------
__device__ __forceinline__ ULL dup2(float v) {
    ULL r;
    asm("mov.b64 %0, {%1, %1};" : "=l"(r) : "f"(v));
    return r;
}
__device__ __forceinline__ ULL pack2(float x, float y) {
    ULL r;
    asm("mov.b64 %0, {%1, %2};" : "=l"(r) : "f"(x), "f"(y));
    return r;
}
__device__ __forceinline__ float2 unpack2(ULL v) {
    float2 f;
    asm("mov.b64 {%0, %1}, %2;" : "=f"(f.x), "=f"(f.y) : "l"(v));
    return f;
}
__device__ __forceinline__ void fma2(ULL& d, ULL a, ULL b) {
    asm("fma.rn.f32x2 %0, %1, %2, %0;" : "+l"(d) : "l"(a), "l"(b));
}
__device__ __forceinline__ void cp16(unsigned saddr, const void* gaddr) {
    asm volatile("cp.async.cg.shared.global [%0], [%1], 16;" :: "r"(saddr), "l"(gaddr));
}
#define CP_COMMIT asm volatile("cp.async.commit_group;" ::: "memory")
#define CP_WAIT0  asm volatile("cp.async.wait_group 0;" ::: "memory")

// ---------------- small prep kernels ----------------
__global__ void prep1_kernel(const float* __restrict__ we0, const float* __restrict__ ae0,
                             const float* __restrict__ we1, const float* __restrict__ ae1,
                             float* __restrict__ vae0, float* __restrict__ vae1) {
    int t = threadIdx.x;
    if (t < DEe) {
        float s = 0.f;
        const float* r = we0 + t * Hh;
        for (int j = 0; j < Hh; j++) s += r[j] * ae0[j];
        vae0[t] = s;
    }
    if (t < Hh) {
        float s = 0.f;
        const float* r = we1 + t * Hh;
        for (int j = 0; j < Hh; j++) s += r[j] * ae1[j];
        vae1[t] = s;
    }
}

__global__ void prep2_kernel(const float* __restrict__ ew0, const float* __restrict__ ew1,
                             const float* __restrict__ eb0, const float* __restrict__ eb1,
                             const float* __restrict__ vae1,
                             float* __restrict__ u, float* __restrict__ c1s,
                             float* __restrict__ ws0, float* __restrict__ ws1,
                             float* __restrict__ Cvec, float* __restrict__ M,
                             float* __restrict__ WA0, float* __restrict__ WB0) {
    int idx = blockIdx.x * blockDim.x + threadIdx.x;
    const float* ewb1 = ew1 + 192 * Hh;
    if (idx < 64) {
        float s = 0.f; const float* r = ew0 + (192 + idx) * Hh;
        for (int j = 0; j < Hh; j++) s += r[j] * vae1[j];
        u[idx] = s;
    } else if (idx == 64) {
        float s = 0.f;
        for (int j = 0; j < Hh; j++) s += eb0[j] * vae1[j];
        c1s[0] = s;
    } else if (idx < 161) {
        int k = idx - 65; float s = 0.f; const float* r = ew0 + k * Hh;
        for (int j = 0; j < Hh; j++) s += r[j] * vae1[j];
        ws0[k] = s;
    } else if (idx < 257) {
        int k = idx - 161; float s = 0.f; const float* r = ew0 + (96 + k) * Hh;
        for (int j = 0; j < Hh; j++) s += r[j] * vae1[j];
        ws1[k] = s;
    } else if (idx < 353) {
        int c = idx - 257; float s = eb1[c];
        for (int j = 0; j < Hh; j++) s += eb0[j] * ewb1[j * Hh + c];
        Cvec[c] = s;
    } else if (idx < 353 + 64 * 96) {
        int t = idx - 353; int k = t / 96, c = t % 96;
        float s = 0.f; const float* r = ew0 + (192 + k) * Hh;
        for (int j = 0; j < Hh; j++) s += r[j] * ewb1[j * Hh + c];
        M[t] = s;
    } else if (idx < 6497 + 96 * 96) {
        int t = idx - 6497; int k = t / 96, c = t % 96;
        float s = 0.f; const float* r = ew0 + k * Hh;
        for (int j = 0; j < Hh; j++) s += r[j] * ewb1[j * Hh + c];
        WA0[t] = s;
    } else if (idx < 15713 + 96 * 96) {
        int t = idx - 15713; int k = t / 96, c = t % 96;
        float s = 0.f; const float* r = ew0 + (96 + k) * Hh;
        for (int j = 0; j < Hh; j++) s += r[j] * ewb1[j * Hh + c];
        WB0[t] = s;
    }
}

// ---------------- CSR build ----------------
__global__ void zero_kernel(int* __restrict__ cnt, int* __restrict__ cursor) {
    int i = blockIdx.x * blockDim.x + threadIdx.x;
    if (i < Nn) { cnt[i] = 0; cursor[i] = 0; }
}

__global__ void hist_kernel(const int* __restrict__ dst, int* __restrict__ cnt) {
    int e = blockIdx.x * blockDim.x + threadIdx.x;
    if (e < Ee) atomicAdd(&cnt[dst[e]], 1);
}

__global__ void scan_kernel(const int* __restrict__ cnt, int* __restrict__ rowstart) {
    __shared__ int ssum[1024];
    const int T = 1024;
    const int CH = (Nn + T - 1) / T;
    int t = threadIdx.x;
    int base = t * CH;
    int s = 0;
    for (int i = 0; i < CH; i++) {
        int idx = base + i;
        if (idx < Nn) s += cnt[idx];
    }
    ssum[t] = s;
    __syncthreads();
    for (int off = 1; off < T; off <<= 1) {
        int v = 0;
        if (t >= off) v = ssum[t - off];
        __syncthreads();
        if (t >= off) ssum[t] += v;
        __syncthreads();
    }
    int run = (t == 0) ? 0 : ssum[t - 1];
    for (int i = 0; i < CH; i++) {
        int idx = base + i;
        if (idx < Nn) { rowstart[idx] = run; run += cnt[idx]; }
    }
    if (t == T - 1) rowstart[Nn] = ssum[T - 1];
}

// half-warp per edge
__global__ void scatter_kernel(const int* __restrict__ src, const int* __restrict__ dst,
                               const float* __restrict__ ea,
                               const int* __restrict__ rowstart, int* __restrict__ cursor,
                               int* __restrict__ srcP, float* __restrict__ t0P, float* __restrict__ t1P,
                               const float* __restrict__ vae0, const float* __restrict__ u) {
    int e = blockIdx.x * (blockDim.x >> 4) + (threadIdx.x >> 4);
    if (e >= Ee) return;
    int sl = threadIdx.x & 15;
    float4 v  = *(const float4*)(ea + (size_t)e * DEe + sl * 4);
    float4 w0 = *(const float4*)(vae0 + sl * 4);
    float4 w1 = *(const float4*)(u + sl * 4);
    float t0 = v.x * w0.x + v.y * w0.y + v.z * w0.z + v.w * w0.w;
    float t1 = v.x * w1.x + v.y * w1.y + v.z * w1.z + v.w * w1.w;
    for (int o = 8; o; o >>= 1) {
        t0 += __shfl_xor_sync(0xffffffffu, t0, o);
        t1 += __shfl_xor_sync(0xffffffffu, t1, o);
    }
    if (sl == 0) {
        int d = dst[e];
        int pos = rowstart[d] + atomicAdd(&cursor[d], 1);
        srcP[pos] = src[e];
        t0P[pos] = t0;
        t1P[pos] = t1;
    }
}

// ---------------- GEMM v7: cp.async double-buffered W, row-pair f32x2 accs ----------------
template<int K, int TWO>
__global__ void __launch_bounds__(192, 4) gemm64(const float* __restrict__ Xa, const float* __restrict__ Wa,
                                                 const float* __restrict__ Xb, const float* __restrict__ Wb,
                                                 float* __restrict__ C) {
    extern __shared__ float sm[];
    float* Xs = sm;                   // [K][64] k-major
    float* Ws = sm + 64 * K;          // [2][16][96]
    const int NC = K / 16;
    int tid = threadIdx.x;
    int cg = tid % 24, rg = tid / 24;
    int col = cg * 4, rbase = rg * 8;
    int r0 = blockIdx.x * 64;
    unsigned wsb = (unsigned)__cvta_generic_to_shared(Ws);

    ULL acc[4][4];
#pragma unroll
    for (int rp = 0; rp < 4; rp++)
#pragma unroll
        for (int c = 0; c < 4; c++) acc[rp][c] = 0ULL;

#pragma unroll
    for (int pass = 0; pass < TWO; pass++) {
        const float* X = pass ? Xb : Xa;
        const float* W = pass ? Wb : Wa;
        if (pass) __syncthreads();
        for (int idx = tid; idx < 64 * (K / 4); idx += 192) {
            int row = idx & 63;
            int kq = idx >> 6;
            float4 v = make_float4(0.f, 0.f, 0.f, 0.f);
            if (r0 + row < Nn) v = *(const float4*)(X + (size_t)(r0 + row) * K + kq * 4);
            Xs[(4 * kq + 0) * 64 + row] = v.x;
            Xs[(4 * kq + 1) * 64 + row] = v.y;
            Xs[(4 * kq + 2) * 64 + row] = v.z;
            Xs[(4 * kq + 3) * 64 + row] = v.w;
        }
        cp16(wsb + tid * 16, (const char*)W + tid * 16);
        cp16(wsb + (tid + 192) * 16, (const char*)W + (tid + 192) * 16);
        CP_COMMIT;
#pragma unroll
        for (int c = 0; c < NC; c++) {
            CP_WAIT0;
            __syncthreads();
            if (c + 1 < NC) {
                unsigned sb = wsb + ((c + 1) & 1) * 6144;
                const char* g = (const char*)(W + (c + 1) * 16 * 96);
                cp16(sb + tid * 16, g + tid * 16);
                cp16(sb + (tid + 192) * 16, g + (tid + 192) * 16);
                CP_COMMIT;
            }
            const float* xk = Xs + c * 16 * 64 + rbase;
            const float4* wrow = (const float4*)(Ws + (c & 1) * 1536) + cg;
#pragma unroll
            for (int k = 0; k < 16; k++) {
                float4 w4 = wrow[k * 24];
                ulonglong2 xa = *(const ulonglong2*)(xk + k * 64);
                ulonglong2 xb = *(const ulonglong2*)(xk + k * 64 + 4);
                ULL wd0 = dup2(w4.x), wd1 = dup2(w4.y), wd2 = dup2(w4.z), wd3 = dup2(w4.w);
                fma2(acc[0][0], xa.x, wd0); fma2(acc[0][1], xa.x, wd1); fma2(acc[0][2], xa.x, wd2); fma2(acc[0][3], xa.x, wd3);
                fma2(acc[1][0], xa.y, wd0); fma2(acc[1][1], xa.y, wd1); fma2(acc[1][2], xa.y, wd2); fma2(acc[1][3], xa.y, wd3);
                fma2(acc[2][0], xb.x, wd0); fma2(acc[2][1], xb.x, wd1); fma2(acc[2][2], xb.x, wd2); fma2(acc[2][3], xb.x, wd3);
                fma2(acc[3][0], xb.y, wd0); fma2(acc[3][1], xb.y, wd1); fma2(acc[3][2], xb.y, wd2); fma2(acc[3][3], xb.y, wd3);
            }
        }
    }

#pragma unroll
    for (int rp = 0; rp < 4; rp++) {
        float2 c0 = unpack2(acc[rp][0]);
        float2 c1 = unpack2(acc[rp][1]);
        float2 c2 = unpack2(acc[rp][2]);
        float2 c3 = unpack2(acc[rp][3]);
        int rowA = r0 + rbase + 2 * rp;
        if (rowA < Nn)
            *(float4*)(C + (size_t)rowA * 96 + col) = make_float4(c0.x, c1.x, c2.x, c3.x);
        if (rowA + 1 < Nn)
            *(float4*)(C + (size_t)(rowA + 1) * 96 + col) = make_float4(c0.y, c1.y, c2.y, c3.y);
    }
}

// ---------------- merged A/B GEMM: 32-row blocks, dual W streams ----------------
// A = x1@ew1_top + xo0@WA0 ; B = x1@ew1_mid + xo0@WB0
// 192 threads = 24 cg x 8 rg; each thread 4 rows x 4 cols for BOTH outputs.
// smem: Xs[96][32] (12KB) + Ws[2 buf][2 mat][16][96] (24KB) = 36KB.
#define AB_SMEM ((96 * 32 + 2 * 2 * 16 * 96) * 4)
__global__ void __launch_bounds__(192) gemm32ab(
    const float* __restrict__ x1, const float* __restrict__ xo0,
    const float* __restrict__ ew1top, const float* __restrict__ ew1mid,
    const float* __restrict__ WA0, const float* __restrict__ WB0,
    float* __restrict__ A, float* __restrict__ B) {
    extern __shared__ float sm[];
    float* Xs = sm;                    // [96][32] k-major
    float* Ws = sm + 96 * 32;          // [2][2][16][96]
    int tid = threadIdx.x;
    int cg = tid % 24, rg = tid / 24;
    int col = cg * 4, rbase = rg * 4;
    int r0 = blockIdx.x * 32;
    unsigned wsb = (unsigned)__cvta_generic_to_shared(Ws);

    ULL accA[2][4], accB[2][4];
#pragma unroll
    for (int rp = 0; rp < 2; rp++)
#pragma unroll
        for (int c = 0; c < 4; c++) { accA[rp][c] = 0ULL; accB[rp][c] = 0ULL; }

#pragma unroll
    for (int pass = 0; pass < 2; pass++) {
        const float* X  = pass ? xo0 : x1;
        const float* WA = pass ? WA0 : ew1top;
        const float* WB = pass ? WB0 : ew1mid;
        if (pass) __syncthreads();
        // Xs k-major transpose load: 32 rows x 24 kquads
        for (int idx = tid; idx < 32 * 24; idx += 192) {
            int row = idx % 32;
            int kq = idx / 32;
            float4 v = make_float4(0.f, 0.f, 0.f, 0.f);
            if (r0 + row < Nn) v = *(const float4*)(X + (size_t)(r0 + row) * 96 + kq * 4);
            Xs[(4 * kq + 0) * 32 + row] = v.x;
            Xs[(4 * kq + 1) * 32 + row] = v.y;
            Xs[(4 * kq + 2) * 32 + row] = v.z;
            Xs[(4 * kq + 3) * 32 + row] = v.w;
        }
        // preload chunk 0 of both W streams (each chunk 6144B = 384 float4)
        cp16(wsb + tid * 16, (const char*)WA + tid * 16);
        cp16(wsb + (tid + 192) * 16, (const char*)WA + (tid + 192) * 16);
        cp16(wsb + 6144 + tid * 16, (const char*)WB + tid * 16);
        cp16(wsb + 6144 + (tid + 192) * 16, (const char*)WB + (tid + 192) * 16);
        CP_COMMIT;
#pragma unroll
        for (int c = 0; c < 6; c++) {      // 96 / 16
            CP_WAIT0;
            __syncthreads();
            if (c + 1 < 6) {
                unsigned sb = wsb + ((c + 1) & 1) * 12288;
                const char* gA = (const char*)(WA + (c + 1) * 16 * 96);
                const char* gB = (const char*)(WB + (c + 1) * 16 * 96);
                cp16(sb + tid * 16, gA + tid * 16);
                cp16(sb + (tid + 192) * 16, gA + (tid + 192) * 16);
                cp16(sb + 6144 + tid * 16, gB + tid * 16);
                cp16(sb + 6144 + (tid + 192) * 16, gB + (tid + 192) * 16);
                CP_COMMIT;
            }
            const float* xk = Xs + c * 16 * 32 + rbase;
            const float4* wrA = (const float4*)(Ws + (c & 1) * 3072) + cg;
            const float4* wrB = (const float4*)(Ws + (c & 1) * 3072 + 1536) + cg;
#pragma unroll
            for (int k = 0; k < 16; k++) {
                float4 wa4 = wrA[k * 24];
                float4 wb4 = wrB[k * 24];
                ulonglong2 xp = *(const ulonglong2*)(xk + k * 32);   // 4 rows (2 pairs)
                ULL a0 = dup2(wa4.x), a1 = dup2(wa4.y), a2 = dup2(wa4.z), a3 = dup2(wa4.w);
                fma2(accA[0][0], xp.x, a0); fma2(accA[0][1], xp.x, a1); fma2(accA[0][2], xp.x, a2); fma2(accA[0][3], xp.x, a3);
                fma2(accA[1][0], xp.y, a0); fma2(accA[1][1], xp.y, a1); fma2(accA[1][2], xp.y, a2); fma2(accA[1][3], xp.y, a3);
                ULL b0 = dup2(wb4.x), b1 = dup2(wb4.y), b2 = dup2(wb4.z), b3 = dup2(wb4.w);
                fma2(accB[0][0], xp.x, b0); fma2(accB[0][1], xp.x, b1); fma2(accB[0][2], xp.x, b2); fma2(accB[0][3], xp.x, b3);
                fma2(accB[1][0], xp.y, b0); fma2(accB[1][1], xp.y, b1); fma2(accB[1][2], xp.y, b2); fma2(accB[1][3], xp.y, b3);
            }
        }
    }

#pragma unroll
    for (int rp = 0; rp < 2; rp++) {
        float2 a0 = unpack2(accA[rp][0]);
        float2 a1 = unpack2(accA[rp][1]);
        float2 a2 = unpack2(accA[rp][2]);
        float2 a3 = unpack2(accA[rp][3]);
        float2 b0 = unpack2(accB[rp][0]);
        float2 b1 = unpack2(accB[rp][1]);
        float2 b2 = unpack2(accB[rp][2]);
        float2 b3 = unpack2(accB[rp][3]);
        int rowA = r0 + rbase + 2 * rp;
        if (rowA < Nn) {
            *(float4*)(A + (size_t)rowA * 96 + col) = make_float4(a0.x, a1.x, a2.x, a3.x);
            *(float4*)(B + (size_t)rowA * 96 + col) = make_float4(b0.x, b1.x, b2.x, b3.x);
        }
        if (rowA + 1 < Nn) {
            *(float4*)(A + (size_t)(rowA + 1) * 96 + col) = make_float4(a0.y, a1.y, a2.y, a3.y);
            *(float4*)(B + (size_t)(rowA + 1) * 96 + col) = make_float4(b0.y, b1.y, b2.y, b3.y);
        }
    }
}

// ---------------- per-row dual/quad dots ----------------
__global__ void row_dots_kernel(const float* __restrict__ H,
                                const float* __restrict__ v1, const float* __restrict__ v2,
                                float* __restrict__ o1, float* __restrict__ o2) {
    int v = blockIdx.x * (blockDim.x >> 5) + (threadIdx.x >> 5);
    if (v >= Nn) return;
    int lane = threadIdx.x & 31;
    const float* hr = H + (size_t)v * Hh;
    float h0 = hr[lane], h1 = hr[lane + 32], h2 = hr[lane + 64];
    float d1 = h0 * v1[lane] + h1 * v1[lane + 32] + h2 * v1[lane + 64];
    float d2 = h0 * v2[lane] + h1 * v2[lane + 32] + h2 * v2[lane + 64];
    for (int o = 16; o; o >>= 1) {
        d1 += __shfl_xor_sync(0xffffffffu, d1, o);
        d2 += __shfl_xor_sync(0xffffffffu, d2, o);
    }
    if (lane == 0) { o1[v] = d1; o2[v] = d2; }
}

__global__ void row_dots4_kernel(const float* __restrict__ H1, const float* __restrict__ X0,
                                 const float* __restrict__ v1, const float* __restrict__ v2,
                                 const float* __restrict__ v3, const float* __restrict__ v4,
                                 float* __restrict__ o1, float* __restrict__ o2,
                                 float* __restrict__ o3, float* __restrict__ o4) {
    int v = blockIdx.x * (blockDim.x >> 5) + (threadIdx.x >> 5);
    if (v >= Nn) return;
    int lane = threadIdx.x & 31;
    const float* hr = H1 + (size_t)v * Hh;
    const float* xr = X0 + (size_t)v * Hh;
    float h0 = hr[lane], h1 = hr[lane + 32], h2 = hr[lane + 64];
    float x0 = xr[lane], x1 = xr[lane + 32], x2 = xr[lane + 64];
    float d1 = h0 * v1[lane] + h1 * v1[lane + 32] + h2 * v1[lane + 64];
    float d2 = h0 * v2[lane] + h1 * v2[lane + 32] + h2 * v2[lane + 64];
    float d3 = x0 * v3[lane] + x1 * v3[lane + 32] + x2 * v3[lane + 64];
    float d4 = x0 * v4[lane] + x1 * v4[lane + 32] + x2 * v4[lane + 64];
    for (int o = 16; o; o >>= 1) {
        d1 += __shfl_xor_sync(0xffffffffu, d1, o);
        d2 += __shfl_xor_sync(0xffffffffu, d2, o);
        d3 += __shfl_xor_sync(0xffffffffu, d3, o);
        d4 += __shfl_xor_sync(0xffffffffu, d4, o);
    }
    if (lane == 0) { o1[v] = d1; o2[v] = d2; o3[v] = d3; o4[v] = d4; }
}

// ---------------- GAT aggregation (warp per destination node) ----------------
__global__ void gat_aggregate_kernel(const int* __restrict__ rowstart, const int* __restrict__ srcP,
                                     float* __restrict__ tP, const float* __restrict__ h,
                                     const float* __restrict__ hs, const float* __restrict__ hd,
                                     const float* __restrict__ svec, const float* __restrict__ sself,
                                     const float* __restrict__ c1s,
                                     const float* __restrict__ bias, float* __restrict__ xout) {
    int v = blockIdx.x * (blockDim.x >> 5) + (threadIdx.x >> 5);
    if (v >= Nn) return;
    int lane = threadIdx.x & 31;
    int s = rowstart[v];
    int deg = rowstart[v + 1] - s;
    float hdv = hd[v];
    float nc = (c1s ? c1s[0] : 0.f) + (sself ? sself[v] : 0.f);
    const float* hv = h + (size_t)v * Hh;
    float den, a0, a1, a2;

    if (deg <= 32) {
        int u = 0;
        float ge = 0.f, l = -INFINITY;
        if (lane < deg) {
            u = srcP[s + lane];
            ge = tP[s + lane] + (svec ? svec[u] : 0.f) + nc;
            float ll = hs[u] + hdv + ge;
            l = ll > 0.f ? ll : 0.2f * ll;
        }
        float gs = (lane < deg) ? ge : 0.f;
        float mx = l;
        for (int o = 16; o; o >>= 1) {
            gs += __shfl_xor_sync(0xffffffffu, gs, o);
            mx = fmaxf(mx, __shfl_xor_sync(0xffffffffu, mx, o));
        }
        float lself = hs[v] + hdv + gs / (deg > 0 ? (float)deg : 1.f);
        lself = lself > 0.f ? lself : 0.2f * lself;
        float m = fmaxf(mx, lself);
        float p = __expf(l - m);
        float psum = p;
        for (int o = 16; o; o >>= 1) psum += __shfl_xor_sync(0xffffffffu, psum, o);
        float ps = __expf(lself - m);
        den = ps + psum;
        a0 = ps * hv[lane]; a1 = ps * hv[lane + 32]; a2 = ps * hv[lane + 64];
        for (int t0 = 0; t0 < deg; t0 += 8) {
            float pp[8]; int uu[8];
#pragma unroll
            for (int t = 0; t < 8; t++) {
                pp[t] = __shfl_sync(0xffffffffu, p, t0 + t);
                uu[t] = __shfl_sync(0xffffffffu, u, t0 + t);
            }
            int cnt8 = min(8, deg - t0);
#pragma unroll
            for (int t = 0; t < 8; t++) {
                if (t < cnt8) {
                    const float* hu = h + (size_t)uu[t] * Hh;
                    a0 = fmaf(pp[t], hu[lane], a0);
                    a1 = fmaf(pp[t], hu[lane + 32], a1);
                    a2 = fmaf(pp[t], hu[lane + 64], a2);
                }
            }
        }
    } else {
        float mx = -INFINITY, gs = 0.f;
        for (int i = lane; i < deg; i += 32) {
            int p_ = s + i;
            int uu = srcP[p_];
            float ge = tP[p_] + (svec ? svec[uu] : 0.f) + nc;
            float l = hs[uu] + hdv + ge;
            l = l > 0.f ? l : 0.2f * l;
            tP[p_] = l;
            gs += ge;
            mx = fmaxf(mx, l);
        }
        for (int o = 16; o; o >>= 1) {
            gs += __shfl_xor_sync(0xffffffffu, gs, o);
            mx = fmaxf(mx, __shfl_xor_sync(0xffffffffu, mx, o));
        }
        __syncwarp();
        float lself = hs[v] + hdv + gs / (float)deg;
        lself = lself > 0.f ? lself : 0.2f * lself;
        float m = fmaxf(mx, lself);
        den = __expf(lself - m);
        a0 = den * hv[lane]; a1 = den * hv[lane + 32]; a2 = den * hv[lane + 64];
        int i = 0;
        while (i < deg) {
            int cnt8 = min(8, deg - i);
            float lg[8]; int us[8];
#pragma unroll
            for (int t = 0; t < 8; t++)
                if (t < cnt8) { lg[t] = tP[s + i + t]; us[t] = srcP[s + i + t]; }
#pragma unroll
            for (int t = 0; t < 8; t++) {
                if (t < cnt8) {
                    float p_ = __expf(lg[t] - m);
                    den += p_;
                    const float* hu = h + (size_t)us[t] * Hh;
                    a0 = fmaf(p_, hu[lane], a0);
                    a1 = fmaf(p_, hu[lane + 32], a1);
                    a2 = fmaf(p_, hu[lane + 64], a2);
                }
            }
            i += cnt8;
        }
    }
    float inv = 1.f / den;
    float* xo = xout + (size_t)v * Hh;
    xo[lane]      = fmaf(a0, inv, bias[lane]);
    xo[lane + 32] = fmaf(a1, inv, bias[lane + 32]);
    xo[lane + 64] = fmaf(a2, inv, bias[lane + 64]);
}

// ---------------- final fused edge kernel v3 (f32x2, 16 edges/thread, unroll 2) ----------------
#define EF3_SMEM ((64 * 96 + 64 * 132) * 4 + 256 * 4)
__global__ void __launch_bounds__(192, 3) edge_final3(
    const float* __restrict__ ea, const int* __restrict__ src, const int* __restrict__ dst,
    const float* __restrict__ A, const float* __restrict__ Bm,
    const float* __restrict__ Mmat, const float* __restrict__ Cvec,
    float* __restrict__ out) {
    extern __shared__ float sm[];
    float* Ms = sm;                       // [64][96]
    float* east = sm + 64 * 96;           // [64][132] transposed ea tile
    int* ss = (int*)(east + 64 * 132);    // [128]
    int* dd = ss + 128;
    int tid = threadIdx.x;
    int cg = tid % 24, eg = tid / 24;
    int col = 4 * cg;
    int ebase = eg * 16;

    for (int idx = tid; idx < 64 * 96; idx += 192) Ms[idx] = Mmat[idx];
    size_t e0 = (size_t)blockIdx.x * 128;
    for (int idx = tid; idx < 4096; idx += 192) {
        int e = idx >> 5;
        int k = (idx & 31) << 1;
        float2 vv = *(const float2*)(ea + (e0 + e) * 64 + k);
        east[k * 132 + e] = vv.x;
        east[(k + 1) * 132 + e] = vv.y;
    }
    if (tid < 128) { ss[tid] = src[e0 + tid]; dd[tid] = dst[e0 + tid]; }
    __syncthreads();

    float4 cv = *(const float4*)(Cvec + col);
    ULL acc[8][4];
#pragma unroll
    for (int p = 0; p < 8; p++) {
        int ei = ebase + 2 * p;
        float4 aL = *(const float4*)(A + (size_t)ss[ei] * 96 + col);
        float4 aR = *(const float4*)(A + (size_t)ss[ei + 1] * 96 + col);
        float4 bL = *(const float4*)(Bm + (size_t)dd[ei] * 96 + col);
        float4 bR = *(const float4*)(Bm + (size_t)dd[ei + 1] * 96 + col);
        acc[p][0] = pack2(cv.x + aL.x + bL.x, cv.x + aR.x + bR.x);
        acc[p][1] = pack2(cv.y + aL.y + bL.y, cv.y + aR.y + bR.y);
        acc[p][2] = pack2(cv.z + aL.z + bL.z, cv.z + aR.z + bR.z);
        acc[p][3] = pack2(cv.w + aL.w + bL.w, cv.w + aR.w + bR.w);
    }

    const float* mrow = Ms + col;
    const float* erow = east + ebase;
#pragma unroll 2
    for (int k = 0; k < 64; k++) {
        float4 m4 = *(const float4*)(mrow + k * 96);
        ULL M0 = dup2(m4.x), M1 = dup2(m4.y), M2 = dup2(m4.z), M3 = dup2(m4.w);
        const float* er = erow + k * 132;
        ulonglong2 q0 = *(const ulonglong2*)(er);
        ulonglong2 q1 = *(const ulonglong2*)(er + 4);
        ulonglong2 q2 = *(const ulonglong2*)(er + 8);
        ulonglong2 q3 = *(const ulonglong2*)(er + 12);
        fma2(acc[0][0], q0.x, M0); fma2(acc[0][1], q0.x, M1); fma2(acc[0][2], q0.x, M2); fma2(acc[0][3], q0.x, M3);
        fma2(acc[1][0], q0.y, M0); fma2(acc[1][1], q0.y, M1); fma2(acc[1][2], q0.y, M2); fma2(acc[1][3], q0.y, M3);
        fma2(acc[2][0], q1.x, M0); fma2(acc[2][1], q1.x, M1); fma2(acc[2][2], q1.x, M2); fma2(acc[2][3], q1.x, M3);
        fma2(acc[3][0], q1.y, M0); fma2(acc[3][1], q1.y, M1); fma2(acc[3][2], q1.y, M2); fma2(acc[3][3], q1.y, M3);
        fma2(acc[4][0], q2.x, M0); fma2(acc[4][1], q2.x, M1); fma2(acc[4][2], q2.x, M2); fma2(acc[4][3], q2.x, M3);
        fma2(acc[5][0], q2.y, M0); fma2(acc[5][1], q2.y, M1); fma2(acc[5][2], q2.y, M2); fma2(acc[5][3], q2.y, M3);
        fma2(acc[6][0], q3.x, M0); fma2(acc[6][1], q3.x, M1); fma2(acc[6][2], q3.x, M2); fma2(acc[6][3], q3.x, M3);
        fma2(acc[7][0], q3.y, M0); fma2(acc[7][1], q3.y, M1); fma2(acc[7][2], q3.y, M2); fma2(acc[7][3], q3.y, M3);
    }

#pragma unroll
    for (int p = 0; p < 8; p++) {
        float2 f0 = unpack2(acc[p][0]);
        float2 f1 = unpack2(acc[p][1]);
        float2 f2 = unpack2(acc[p][2]);
        float2 f3 = unpack2(acc[p][3]);
        size_t eA = e0 + ebase + 2 * p;
        *(float4*)(out + eA * 96 + col)       = make_float4(f0.x, f1.x, f2.x, f3.x);
        *(float4*)(out + (eA + 1) * 96 + col) = make_float4(f0.y, f1.y, f2.y, f3.y);
    }
}

// ---------------- host ----------------
static void* sym(const void* s) {
    void* p = nullptr;
    cudaGetSymbolAddress(&p, (const void*)s);
    return p;
}

extern "C" void kernel_launch(void* const* d_in, const int* in_sizes, int n_in,
                              void* d_out, int out_size) {
    const float* x    = (const float*)d_in[0];
    const int*   ei   = (const int*)d_in[1];
    const float* ea   = (const float*)d_in[2];
    const float* w0   = (const float*)d_in[3];
    const float* we0  = (const float*)d_in[4];
    const float* as0  = (const float*)d_in[5];
    const float* ad0  = (const float*)d_in[6];
    const float* ae0  = (const float*)d_in[7];
    const float* b0   = (const float*)d_in[8];
    const float* ew0  = (const float*)d_in[9];
    const float* eb0  = (const float*)d_in[10];
    const float* w1   = (const float*)d_in[11];
    const float* we1  = (const float*)d_in[12];
    const float* as1  = (const float*)d_in[13];
    const float* ad1  = (const float*)d_in[14];
    const float* ae1  = (const float*)d_in[15];
    const float* b1   = (const float*)d_in[16];
    const float* ew1  = (const float*)d_in[17];
    const float* eb1  = (const float*)d_in[18];

    const int* src = ei;
    const int* dst = ei + Ee;

    float* h0   = (float*)sym(d_h0);
    float* xo0  = (float*)sym(d_xo0);
    float* h1   = (float*)sym(d_h1);
    float* A    = (float*)sym(d_A);
    float* B    = (float*)sym(d_B);
    float* hs0  = (float*)sym(d_hs0);
    float* hd0  = (float*)sym(d_hd0);
    float* hs1  = (float*)sym(d_hs1);
    float* hd1  = (float*)sym(d_hd1);
    float* s0   = (float*)sym(d_s0);
    float* s1   = (float*)sym(d_s1);
    int*   cnt  = (int*)sym(d_cnt);
    int*   rowstart = (int*)sym(d_rowstart);
    int*   cursor   = (int*)sym(d_cursor);
    int*   srcP = (int*)sym(d_srcP);
    float* t0P  = (float*)sym(d_t0P);
    float* t1P  = (float*)sym(d_t1P);
    float* vae0 = (float*)sym(d_vae0);
    float* vae1 = (float*)sym(d_vae1);
    float* u    = (float*)sym(d_u);
    float* ws0  = (float*)sym(d_ws0);
    float* ws1  = (float*)sym(d_ws1);
    float* Cvec = (float*)sym(d_Cvec);
    float* M    = (float*)sym(d_M);
    float* WA0  = (float*)sym(d_WA0);
    float* WB0  = (float*)sym(d_WB0);
    float* c1s  = (float*)sym(d_c1s);

    float* x1_out = (float*)d_out;                       // [Nn,96]
    float* ea_out = (float*)d_out + (size_t)Nn * Hh;     // [Ee,96]

    const int SM128 = (64 * 128 + 2 * 16 * 96) * 4;   // 44KB
    const int SM96  = (64 * 96 + 2 * 16 * 96) * 4;    // 36KB
    cudaFuncSetAttribute(edge_final3, cudaFuncAttributeMaxDynamicSharedMemorySize, EF3_SMEM);

    const int GB = (Nn + 63) / 64;

    // prep + CSR
    zero_kernel<<<(Nn + 255) / 256, 256>>>(cnt, cursor);
    prep1_kernel<<<1, 96>>>(we0, ae0, we1, ae1, vae0, vae1);
    prep2_kernel<<<(24929 + 127) / 128, 128>>>(ew0, ew1, eb0, eb1, vae1,
                                               u, c1s, ws0, ws1, Cvec, M, WA0, WB0);
    gemm64<128, 1><<<GB, 192, SM128>>>(x, w0, nullptr, nullptr, h0);          // h0 = x@w0 (profiled)
    hist_kernel<<<Ee / 256, 256>>>(dst, cnt);
    scan_kernel<<<1, 1024>>>(cnt, rowstart);
    scatter_kernel<<<Ee / 16, 256>>>(src, dst, ea, rowstart, cursor, srcP, t0P, t1P, vae0, u);

    // layer 0
    row_dots_kernel<<<Nn / 8, 256>>>(h0, as0, ad0, hs0, hd0);
    gat_aggregate_kernel<<<Nn / 8, 256>>>(rowstart, srcP, t0P, h0, hs0, hd0,
                                          nullptr, nullptr, nullptr, b0, xo0);

    // layer 1 node path
    gemm64<96, 1><<<GB, 192, SM96>>>(xo0, w1, nullptr, nullptr, h1);          // h1 = xo0@w1
    row_dots4_kernel<<<Nn / 8, 256>>>(h1, xo0, as1, ad1, ws0, ws1, hs1, hd1, s0, s1);
    gat_aggregate_kernel<<<Nn / 8, 256>>>(rowstart, srcP, t1P, h1, hs1, hd1,
                                          s0, s1, c1s, b1, x1_out);

    // A = x1@ew1_top + xo0@WA0 ; B = x1@ew1_mid + xo0@WB0  (merged, dual-output)
    gemm32ab<<<(Nn + 31) / 32, 192, AB_SMEM>>>(x1_out, xo0, ew1, ew1 + 96 * 96, WA0, WB0, A, B);

    // fused final edge output (128-edge tiles, the R9 configuration)
    edge_final3<<<Ee / 128, 192, EF3_SMEM>>>(ea, src, dst, A, B, M, Cvec, ea_out);
}